// round 1
// baseline (speedup 1.0000x reference)
#include <cuda_runtime.h>
#include <math.h>

#define BN 4
#define NN 256
#define EFD 256
#define MD 128
#define CLS 600

// ---------------- device scratch (static, zero-init) ----------------
__device__ float g_mraw[(size_t)BN * NN * NN * MD];   // 128 MB
__device__ float g_sA[BN * NN * NN];
__device__ float g_sB[BN * NN * NN];
__device__ float g_nf[BN * NN * MD];
__device__ float g_anf[BN * NN * MD];
__device__ float g_msum[BN * NN * MD];
__device__ int   g_valid[BN];

__device__ __forceinline__ float sigmoidf_(float x) {
    return 1.0f / (1.0f + __expf(-x));
}

// ---------------- tiny: valid counts ----------------
__global__ void k_valid(const int* __restrict__ hn, const int* __restrict__ on) {
    int b = threadIdx.x;
    if (b < BN) g_valid[b] = hn[b] + on[b];
}

// ---------------- zero the pred_adj region of the output ----------------
__global__ void k_zero_adj(float* __restrict__ out) {
    int idx = blockIdx.x * blockDim.x + threadIdx.x;   // covers BN*NN*NN/4 float4
    float4 z = make_float4(0.f, 0.f, 0.f, 0.f);
    reinterpret_cast<float4*>(out)[idx] = z;
}

// ---------------- node features: nf = x@W_nr+b ; a_nf = nf@W_msg_top+b_msg ----------------
// 8 nodes per block, 128 threads (thread = output column)
__global__ __launch_bounds__(128) void k_nodes(
    const float* __restrict__ nfeat,
    const float* __restrict__ W_nr, const float* __restrict__ b_nr,
    const float* __restrict__ W_msg, const float* __restrict__ b_msg)
{
    const int t = threadIdx.x;
    const int g0 = blockIdx.x * 8;        // global node base (b*N + n flattened)
    __shared__ float xs[8][EFD];          // 8 KB
    __shared__ float nfs[8][MD];          // 4 KB

    { // load 8 rows of 256 floats, vectorized
        const float4* src = reinterpret_cast<const float4*>(nfeat + (size_t)g0 * EFD);
        float4* dst = reinterpret_cast<float4*>(&xs[0][0]);
        #pragma unroll
        for (int j = 0; j < 4; j++) dst[t + 128 * j] = src[t + 128 * j];
    }
    __syncthreads();

    float acc[8];
    #pragma unroll
    for (int n = 0; n < 8; n++) acc[n] = 0.f;
    for (int k = 0; k < EFD; k++) {
        float wv = W_nr[k * MD + t];
        #pragma unroll
        for (int n = 0; n < 8; n++) acc[n] = fmaf(xs[n][k], wv, acc[n]);
    }
    float bv = b_nr[t];
    #pragma unroll
    for (int n = 0; n < 8; n++) {
        float v = acc[n] + bv;
        nfs[n][t] = v;
        g_nf[(size_t)(g0 + n) * MD + t] = v;
    }
    __syncthreads();

    #pragma unroll
    for (int n = 0; n < 8; n++) acc[n] = 0.f;
    for (int k = 0; k < MD; k++) {
        float wv = W_msg[k * MD + t];   // top half rows of W_msg
        #pragma unroll
        for (int n = 0; n < 8; n++) acc[n] = fmaf(nfs[n][k], wv, acc[n]);
    }
    bv = b_msg[t];
    #pragma unroll
    for (int n = 0; n < 8; n++)
        g_anf[(size_t)(g0 + n) * MD + t] = acc[n] + bv;
}

// ---------------- big edge kernel: ef -> m_raw, s0 ----------------
// tile = 4 receivers x 16 senders = 64 edges, 128 threads.
// thread (rg = warp 0..3, cg = lane 0..31): rows rg*16..rg*16+15, cols cg + {0,32,64,96}
__global__ __launch_bounds__(128) void k_edge(
    const float* __restrict__ X,
    const float* __restrict__ W_er, const float* __restrict__ b_er,
    const float* __restrict__ W_msg,
    const float* __restrict__ W_l1, const float* __restrict__ b_l1,
    const float* __restrict__ W_l2, const float* __restrict__ b_l2)
{
    const int b  = blockIdx.z;
    const int V  = g_valid[b];
    const int i0 = blockIdx.y * 4;
    const int w0 = blockIdx.x * 16;
    if (i0 >= V || w0 >= V) return;

    const int t  = threadIdx.x;
    const int cg = t & 31;
    const int rg = t >> 5;

    __shared__ float xs[64][16];       // 4 KB  (activation k-chunk, per-warp rows)
    __shared__ float ws[16][MD];       // 8 KB  (weight k-chunk)
    __shared__ float efs[64][MD];      // 32 KB (ef tile)

    int  ebase[16];
    bool rok[16];
    #pragma unroll
    for (int r = 0; r < 16; r++) {
        int lr = rg * 16 + r;
        int i = i0 + (lr >> 4);
        int w = w0 + (lr & 15);
        ebase[r] = (b * NN + i) * NN + w;
        rok[r]   = (i < V) && (w < V);
    }

    float acc[16][4];

    // ---- stage 1: ef = X @ W_er  (K = 256) ----
    #pragma unroll
    for (int r = 0; r < 16; r++) { acc[r][0]=0.f; acc[r][1]=0.f; acc[r][2]=0.f; acc[r][3]=0.f; }

    for (int k0 = 0; k0 < EFD; k0 += 16) {
        { // xs: warp loads its own 16 rows x 16 k
            int r2 = cg >> 4;           // 0..1
            int kk = cg & 15;
            #pragma unroll
            for (int rr = 0; rr < 8; rr++) {
                int row = rr * 2 + r2;
                xs[rg * 16 + row][kk] = X[(size_t)ebase[row] * EFD + k0 + kk];
            }
        }
        { // ws: 16 x 128 weights
            int kk = t >> 3, cs = (t & 7) * 16;
            const float4* s4 = reinterpret_cast<const float4*>(W_er + (size_t)(k0 + kk) * MD + cs);
            float4* d4 = reinterpret_cast<float4*>(&ws[kk][cs]);
            #pragma unroll
            for (int j = 0; j < 4; j++) d4[j] = s4[j];
        }
        __syncthreads();
        #pragma unroll
        for (int kk = 0; kk < 16; kk++) {
            float wa = ws[kk][cg], wb = ws[kk][cg+32], wc = ws[kk][cg+64], wd = ws[kk][cg+96];
            #pragma unroll
            for (int r = 0; r < 16; r++) {
                float xv = xs[rg * 16 + r][kk];
                acc[r][0] = fmaf(xv, wa, acc[r][0]);
                acc[r][1] = fmaf(xv, wb, acc[r][1]);
                acc[r][2] = fmaf(xv, wc, acc[r][2]);
                acc[r][3] = fmaf(xv, wd, acc[r][3]);
            }
        }
        __syncthreads();
    }
    { // ef = acc + b_er -> efs
        float e0 = b_er[cg], e1 = b_er[cg+32], e2 = b_er[cg+64], e3 = b_er[cg+96];
        #pragma unroll
        for (int r = 0; r < 16; r++) {
            efs[rg*16+r][cg]    = acc[r][0] + e0;
            efs[rg*16+r][cg+32] = acc[r][1] + e1;
            efs[rg*16+r][cg+64] = acc[r][2] + e2;
            efs[rg*16+r][cg+96] = acc[r][3] + e3;
        }
    }
    __syncthreads();

    // ---- stage 2: m_raw = relu(ef @ W_msg_bot + a_nf[w])  (K = 128) ----
    #pragma unroll
    for (int r = 0; r < 16; r++) { acc[r][0]=0.f; acc[r][1]=0.f; acc[r][2]=0.f; acc[r][3]=0.f; }
    for (int k0 = 0; k0 < MD; k0 += 16) {
        {
            int kk = t >> 3, cs = (t & 7) * 16;
            const float4* s4 = reinterpret_cast<const float4*>(W_msg + (size_t)(MD + k0 + kk) * MD + cs);
            float4* d4 = reinterpret_cast<float4*>(&ws[kk][cs]);
            #pragma unroll
            for (int j = 0; j < 4; j++) d4[j] = s4[j];
        }
        __syncthreads();
        #pragma unroll
        for (int kk = 0; kk < 16; kk++) {
            float wa = ws[kk][cg], wb = ws[kk][cg+32], wc = ws[kk][cg+64], wd = ws[kk][cg+96];
            #pragma unroll
            for (int r = 0; r < 16; r++) {
                float xv = efs[rg * 16 + r][k0 + kk];
                acc[r][0] = fmaf(xv, wa, acc[r][0]);
                acc[r][1] = fmaf(xv, wb, acc[r][1]);
                acc[r][2] = fmaf(xv, wc, acc[r][2]);
                acc[r][3] = fmaf(xv, wd, acc[r][3]);
            }
        }
        __syncthreads();
    }
    #pragma unroll
    for (int r = 0; r < 16; r++) {
        if (!rok[r]) continue;
        int lr = rg * 16 + r;
        int w = w0 + (lr & 15);
        const float* ap = g_anf + (size_t)(b * NN + w) * MD;
        float* mp = g_mraw + (size_t)ebase[r] * MD;
        mp[cg]    = fmaxf(acc[r][0] + ap[cg],    0.f);
        mp[cg+32] = fmaxf(acc[r][1] + ap[cg+32], 0.f);
        mp[cg+64] = fmaxf(acc[r][2] + ap[cg+64], 0.f);
        mp[cg+96] = fmaxf(acc[r][3] + ap[cg+96], 0.f);
    }

    // ---- stage 3: s0 = relu(ef @ W_l1 + b_l1) . W_l2 + b_l2 ----
    #pragma unroll
    for (int r = 0; r < 16; r++) { acc[r][0]=0.f; acc[r][1]=0.f; acc[r][2]=0.f; acc[r][3]=0.f; }
    for (int k0 = 0; k0 < MD; k0 += 16) {
        {
            int kk = t >> 3, cs = (t & 7) * 16;
            const float4* s4 = reinterpret_cast<const float4*>(W_l1 + (size_t)(k0 + kk) * MD + cs);
            float4* d4 = reinterpret_cast<float4*>(&ws[kk][cs]);
            #pragma unroll
            for (int j = 0; j < 4; j++) d4[j] = s4[j];
        }
        __syncthreads();
        #pragma unroll
        for (int kk = 0; kk < 16; kk++) {
            float wa = ws[kk][cg], wb = ws[kk][cg+32], wc = ws[kk][cg+64], wd = ws[kk][cg+96];
            #pragma unroll
            for (int r = 0; r < 16; r++) {
                float xv = efs[rg * 16 + r][k0 + kk];
                acc[r][0] = fmaf(xv, wa, acc[r][0]);
                acc[r][1] = fmaf(xv, wb, acc[r][1]);
                acc[r][2] = fmaf(xv, wc, acc[r][2]);
                acc[r][3] = fmaf(xv, wd, acc[r][3]);
            }
        }
        __syncthreads();
    }
    {
        float l0 = b_l1[cg], l1 = b_l1[cg+32], l2 = b_l1[cg+64], l3 = b_l1[cg+96];
        float u0 = W_l2[cg], u1 = W_l2[cg+32], u2 = W_l2[cg+64], u3 = W_l2[cg+96];
        float bl2 = b_l2[0];
        #pragma unroll
        for (int r = 0; r < 16; r++) {
            float p = fmaxf(acc[r][0] + l0, 0.f) * u0
                    + fmaxf(acc[r][1] + l1, 0.f) * u1
                    + fmaxf(acc[r][2] + l2, 0.f) * u2
                    + fmaxf(acc[r][3] + l3, 0.f) * u3;
            #pragma unroll
            for (int o = 16; o > 0; o >>= 1) p += __shfl_xor_sync(0xffffffffu, p, o);
            if (cg == 0 && rok[r]) {
                g_sA[ebase[r]] = p + bl2;
            }
        }
    }
}

// ---------------- rounds 1 & 2: s_next[i,w] = f(sigmoid(s_prev[w,i]) * m_raw[w,i]) ----------------
__global__ __launch_bounds__(128) void k_round(
    int pass,
    const float* __restrict__ W_l1, const float* __restrict__ b_l1,
    const float* __restrict__ W_l2, const float* __restrict__ b_l2,
    float* __restrict__ out_adj)   // non-null on final pass
{
    const int b  = blockIdx.z;
    const int V  = g_valid[b];
    const int i0 = blockIdx.y * 4;
    const int w0 = blockIdx.x * 16;
    if (i0 >= V || w0 >= V) return;

    const float* sprev = (pass == 1) ? g_sA : g_sB;
    float*       snext = (pass == 1) ? g_sB : g_sA;

    const int t  = threadIdx.x;
    const int cg = t & 31;
    const int rg = t >> 5;

    __shared__ float vs[64][MD];   // 32 KB
    __shared__ float ws[16][MD];   // 8 KB

    bool rok[16];
    int  dbase[16];
    #pragma unroll
    for (int r = 0; r < 16; r++) {
        int lr = rg * 16 + r;
        int i = i0 + (lr >> 4);
        int w = w0 + (lr & 15);
        rok[r]   = (i < V) && (w < V);
        dbase[r] = (b * NN + i) * NN + w;
        int sed  = (b * NN + w) * NN + i;   // transposed edge
        float g = 0.f;
        if (rok[r]) g = sigmoidf_(sprev[sed]);
        const float* mp = g_mraw + (size_t)sed * MD;
        if (rok[r]) {
            vs[lr][cg]    = g * mp[cg];
            vs[lr][cg+32] = g * mp[cg+32];
            vs[lr][cg+64] = g * mp[cg+64];
            vs[lr][cg+96] = g * mp[cg+96];
        } else {
            vs[lr][cg] = 0.f; vs[lr][cg+32] = 0.f; vs[lr][cg+64] = 0.f; vs[lr][cg+96] = 0.f;
        }
    }

    float acc[16][4];
    #pragma unroll
    for (int r = 0; r < 16; r++) { acc[r][0]=0.f; acc[r][1]=0.f; acc[r][2]=0.f; acc[r][3]=0.f; }

    for (int k0 = 0; k0 < MD; k0 += 16) {
        {
            int kk = t >> 3, cs = (t & 7) * 16;
            const float4* s4 = reinterpret_cast<const float4*>(W_l1 + (size_t)(k0 + kk) * MD + cs);
            float4* d4 = reinterpret_cast<float4*>(&ws[kk][cs]);
            #pragma unroll
            for (int j = 0; j < 4; j++) d4[j] = s4[j];
        }
        __syncthreads();
        #pragma unroll
        for (int kk = 0; kk < 16; kk++) {
            float wa = ws[kk][cg], wb = ws[kk][cg+32], wc = ws[kk][cg+64], wd = ws[kk][cg+96];
            #pragma unroll
            for (int r = 0; r < 16; r++) {
                float xv = vs[rg * 16 + r][k0 + kk];
                acc[r][0] = fmaf(xv, wa, acc[r][0]);
                acc[r][1] = fmaf(xv, wb, acc[r][1]);
                acc[r][2] = fmaf(xv, wc, acc[r][2]);
                acc[r][3] = fmaf(xv, wd, acc[r][3]);
            }
        }
        __syncthreads();
    }
    {
        float l0 = b_l1[cg], l1 = b_l1[cg+32], l2 = b_l1[cg+64], l3 = b_l1[cg+96];
        float u0 = W_l2[cg], u1 = W_l2[cg+32], u2 = W_l2[cg+64], u3 = W_l2[cg+96];
        float bl2 = b_l2[0];
        #pragma unroll
        for (int r = 0; r < 16; r++) {
            float p = fmaxf(acc[r][0] + l0, 0.f) * u0
                    + fmaxf(acc[r][1] + l1, 0.f) * u1
                    + fmaxf(acc[r][2] + l2, 0.f) * u2
                    + fmaxf(acc[r][3] + l3, 0.f) * u3;
            #pragma unroll
            for (int o = 16; o > 0; o >>= 1) p += __shfl_xor_sync(0xffffffffu, p, o);
            if (cg == 0 && rok[r]) {
                float sv = p + bl2;
                snext[dbase[r]] = sv;
                if (out_adj) out_adj[dbase[r]] = sv;
            }
        }
    }
}

// ---------------- m_sum[b,i] = sum_w sigmoid(s2[i,w]) * m_raw[i,w,:] ----------------
__global__ __launch_bounds__(128) void k_msum() {
    const int b = blockIdx.y;
    const int i = blockIdx.x;
    const int V = g_valid[b];
    const int t = threadIdx.x;
    float a0 = 0.f, a1 = 0.f;
    if (i < V) {
        const float* sp = g_sA + (b * NN + i) * NN;   // s2 lives in g_sA after pass 2
        const float* mp = g_mraw + (size_t)(b * NN + i) * NN * MD;
        int w = 0;
        for (; w + 1 < V; w += 2) {
            float ga = sigmoidf_(sp[w]);
            float gb = sigmoidf_(sp[w + 1]);
            a0 = fmaf(ga, mp[(size_t)w * MD + t], a0);
            a1 = fmaf(gb, mp[(size_t)(w + 1) * MD + t], a1);
        }
        if (w < V) {
            float ga = sigmoidf_(sp[w]);
            a0 = fmaf(ga, mp[(size_t)w * MD + t], a0);
        }
    }
    g_msum[(size_t)(b * NN + i) * MD + t] = a0 + a1;
}

// ---------------- GRU + readout, 8 nodes per block ----------------
__global__ __launch_bounds__(128) void k_gru(
    const float* __restrict__ W_ih, const float* __restrict__ b_ih,
    const float* __restrict__ W_hh, const float* __restrict__ b_hh,
    const float* __restrict__ W_ro, const float* __restrict__ b_ro,
    float* __restrict__ out)
{
    const int b  = blockIdx.y;
    const int V  = g_valid[b];
    const int i0 = blockIdx.x * 8;
    const int t  = threadIdx.x;

    __shared__ float ms[8][MD];
    __shared__ float hsn[8][MD];
    __shared__ float hnew[8][MD];

    #pragma unroll
    for (int n = 0; n < 8; n++) {
        ms[n][t]  = g_msum[(size_t)(b * NN + i0 + n) * MD + t];
        hsn[n][t] = g_nf[(size_t)(b * NN + i0 + n) * MD + t];
    }
    __syncthreads();

    float air[8], aiz[8], ain[8], ahr[8], ahz[8], ahn[8];
    {
        float bir = b_ih[t], biz = b_ih[128 + t], bin_ = b_ih[256 + t];
        float bhr = b_hh[t], bhz = b_hh[128 + t], bhn = b_hh[256 + t];
        #pragma unroll
        for (int n = 0; n < 8; n++) {
            air[n] = bir; aiz[n] = biz; ain[n] = bin_;
            ahr[n] = bhr; ahz[n] = bhz; ahn[n] = bhn;
        }
    }
    for (int k = 0; k < MD; k++) {
        float wr = W_ih[k * 384 + t];
        float wz = W_ih[k * 384 + 128 + t];
        float wn = W_ih[k * 384 + 256 + t];
        float vr = W_hh[k * 384 + t];
        float vz = W_hh[k * 384 + 128 + t];
        float vn = W_hh[k * 384 + 256 + t];
        #pragma unroll
        for (int n = 0; n < 8; n++) {
            float xv = ms[n][k], hv = hsn[n][k];
            air[n] = fmaf(xv, wr, air[n]);
            aiz[n] = fmaf(xv, wz, aiz[n]);
            ain[n] = fmaf(xv, wn, ain[n]);
            ahr[n] = fmaf(hv, vr, ahr[n]);
            ahz[n] = fmaf(hv, vz, ahz[n]);
            ahn[n] = fmaf(hv, vn, ahn[n]);
        }
    }
    #pragma unroll
    for (int n = 0; n < 8; n++) {
        float r  = sigmoidf_(air[n] + ahr[n]);
        float z  = sigmoidf_(aiz[n] + ahz[n]);
        float nn_ = tanhf(ain[n] + r * ahn[n]);
        hnew[n][t] = (1.f - z) * nn_ + z * hsn[n][t];
    }
    __syncthreads();

    // labels: 600 output classes, 5 column-blocks of 128
    float* lab = out + (size_t)BN * NN * NN;
    for (int cb = 0; cb < 5; cb++) {
        int c = cb * 128 + t;
        if (c >= CLS) continue;
        float lacc[8];
        #pragma unroll
        for (int n = 0; n < 8; n++) lacc[n] = 0.f;
        for (int k = 0; k < MD; k++) {
            float wv = W_ro[k * CLS + c];
            #pragma unroll
            for (int n = 0; n < 8; n++) lacc[n] = fmaf(hnew[n][k], wv, lacc[n]);
        }
        float bv = b_ro[c];
        #pragma unroll
        for (int n = 0; n < 8; n++) {
            int i = i0 + n;
            float v = (i < V) ? (lacc[n] + bv) : 0.f;
            lab[(size_t)(b * NN + i) * CLS + c] = v;
        }
    }
}

// ---------------- launcher ----------------
extern "C" void kernel_launch(void* const* d_in, const int* in_sizes, int n_in,
                              void* d_out, int out_size)
{
    const float* edge_features = (const float*)d_in[0];
    const float* node_features = (const float*)d_in[1];
    const int*   human = (const int*)d_in[4];
    const int*   obj   = (const int*)d_in[5];
    const float* W_er  = (const float*)d_in[6];
    const float* b_er  = (const float*)d_in[7];
    const float* W_nr  = (const float*)d_in[8];
    const float* b_nr  = (const float*)d_in[9];
    const float* W_l1  = (const float*)d_in[10];
    const float* b_l1  = (const float*)d_in[11];
    const float* W_l2  = (const float*)d_in[12];
    const float* b_l2  = (const float*)d_in[13];
    const float* W_msg = (const float*)d_in[14];
    const float* b_msg = (const float*)d_in[15];
    const float* W_ih  = (const float*)d_in[16];
    const float* b_ih  = (const float*)d_in[17];
    const float* W_hh  = (const float*)d_in[18];
    const float* b_hh  = (const float*)d_in[19];
    const float* W_ro  = (const float*)d_in[20];
    const float* b_ro  = (const float*)d_in[21];
    float* out = (float*)d_out;

    k_valid<<<1, 32>>>(human, obj);
    k_zero_adj<<<256, 256>>>(out);                 // BN*NN*NN/4 float4 exactly
    k_nodes<<<128, 128>>>(node_features, W_nr, b_nr, W_msg, b_msg);

    dim3 eg(NN / 16, NN / 4, BN);
    k_edge<<<eg, 128>>>(edge_features, W_er, b_er, W_msg, W_l1, b_l1, W_l2, b_l2);
    k_round<<<eg, 128>>>(1, W_l1, b_l1, W_l2, b_l2, nullptr);
    k_round<<<eg, 128>>>(2, W_l1, b_l1, W_l2, b_l2, out);   // writes pred_adj + s2 (g_sA)

    dim3 mg(NN, BN);
    k_msum<<<mg, 128>>>();
    k_gru<<<dim3(NN / 8, BN), 128>>>(W_ih, b_ih, W_hh, b_hh, W_ro, b_ro, out);
}

// round 2
// speedup vs baseline: 1.0958x; 1.0958x over previous
#include <cuda_runtime.h>
#include <math.h>

#define BN 4
#define NN 256
#define EFD 256
#define MD 128
#define CLS 600

// ---------------- device scratch (static, zero-init) ----------------
__device__ float g_mraw[(size_t)BN * NN * NN * MD];   // 128 MB
__device__ float g_sA[BN * NN * NN];
__device__ float g_sB[BN * NN * NN];
__device__ float g_nf[BN * NN * MD];
__device__ float g_anf[BN * NN * MD];
__device__ float g_msum[BN * NN * MD];
__device__ int   g_valid[BN];

__device__ __forceinline__ float sigmoidf_(float x) {
    return 1.0f / (1.0f + __expf(-x));
}

// ---------------- tiny: valid counts ----------------
__global__ void k_valid(const int* __restrict__ hn, const int* __restrict__ on) {
    int b = threadIdx.x;
    if (b < BN) g_valid[b] = hn[b] + on[b];
}

// ---------------- zero the pred_adj region of the output ----------------
__global__ void k_zero_adj(float* __restrict__ out) {
    int idx = blockIdx.x * blockDim.x + threadIdx.x;   // covers BN*NN*NN/4 float4
    float4 z = make_float4(0.f, 0.f, 0.f, 0.f);
    reinterpret_cast<float4*>(out)[idx] = z;
}

// ---------------- node features: nf = x@W_nr+b ; a_nf = nf@W_msg_top+b_msg ----------------
__global__ __launch_bounds__(128) void k_nodes(
    const float* __restrict__ nfeat,
    const float* __restrict__ W_nr, const float* __restrict__ b_nr,
    const float* __restrict__ W_msg, const float* __restrict__ b_msg)
{
    const int t = threadIdx.x;
    const int g0 = blockIdx.x * 8;        // global node base (b*N + n flattened)
    __shared__ float xs[8][EFD];          // 8 KB
    __shared__ float nfs[8][MD];          // 4 KB

    { // load 8 rows of 256 floats, vectorized
        const float4* src = reinterpret_cast<const float4*>(nfeat + (size_t)g0 * EFD);
        float4* dst = reinterpret_cast<float4*>(&xs[0][0]);
        #pragma unroll
        for (int j = 0; j < 4; j++) dst[t + 128 * j] = src[t + 128 * j];
    }
    __syncthreads();

    float acc[8];
    #pragma unroll
    for (int n = 0; n < 8; n++) acc[n] = 0.f;
    for (int k = 0; k < EFD; k++) {
        float wv = W_nr[k * MD + t];
        #pragma unroll
        for (int n = 0; n < 8; n++) acc[n] = fmaf(xs[n][k], wv, acc[n]);
    }
    float bv = b_nr[t];
    #pragma unroll
    for (int n = 0; n < 8; n++) {
        float v = acc[n] + bv;
        nfs[n][t] = v;
        g_nf[(size_t)(g0 + n) * MD + t] = v;
    }
    __syncthreads();

    #pragma unroll
    for (int n = 0; n < 8; n++) acc[n] = 0.f;
    for (int k = 0; k < MD; k++) {
        float wv = W_msg[k * MD + t];   // top half rows of W_msg
        #pragma unroll
        for (int n = 0; n < 8; n++) acc[n] = fmaf(nfs[n][k], wv, acc[n]);
    }
    bv = b_msg[t];
    #pragma unroll
    for (int n = 0; n < 8; n++)
        g_anf[(size_t)(g0 + n) * MD + t] = acc[n] + bv;
}

// ---------------- big edge kernel: ef -> m_raw, s0 ----------------
// tile = 4 receivers x 16 senders = 64 edges, 128 threads (4 warps).
// warp rg owns rows rg*16..+15; lane cg owns 4 CONTIGUOUS cols c0=cg*4.
__global__ __launch_bounds__(128, 4) void k_edge(
    const float* __restrict__ X,
    const float* __restrict__ W_er, const float* __restrict__ b_er,
    const float* __restrict__ W_msg,
    const float* __restrict__ W_l1, const float* __restrict__ b_l1,
    const float* __restrict__ W_l2, const float* __restrict__ b_l2)
{
    const int b  = blockIdx.z;
    const int V  = g_valid[b];
    const int i0 = blockIdx.y * 4;
    const int w0 = blockIdx.x * 16;
    if (i0 >= V || w0 >= V) return;
    const int Vi = V - i0;           // valid receivers in tile (clip at 4)
    const int Vw = V - w0;           // valid senders in tile (clip at 16)

    const int t  = threadIdx.x;
    const int cg = t & 31;
    const int rg = t >> 5;
    const int c0 = cg * 4;
    const int ebase0 = (b * NN + i0) * NN + w0;   // edge idx of tile row 0

    __shared__ float xs[64][17];       // 4.25 KB (activation k-chunk)
    __shared__ float ws[16][MD];       // 8 KB    (weight k-chunk)
    __shared__ float efs[64][MD];      // 32 KB   (ef tile)

    float acc[16][4];

    // ---- stage 1: ef = X @ W_er  (K = 256) ----
    #pragma unroll
    for (int r = 0; r < 16; r++) { acc[r][0]=0.f; acc[r][1]=0.f; acc[r][2]=0.f; acc[r][3]=0.f; }

    for (int k0 = 0; k0 < EFD; k0 += 16) {
        { // xs: warp loads its own 16 rows x 16 k (scalar, 64B-coalesced)
            int r2 = cg >> 4;           // 0..1
            int kk = cg & 15;
            #pragma unroll
            for (int rr = 0; rr < 8; rr++) {
                int row = rr * 2 + r2;
                int lr  = rg * 16 + row;
                int e   = ebase0 + (lr >> 4) * NN + (lr & 15);
                xs[lr][kk] = X[(size_t)e * EFD + k0 + kk];
            }
        }
        { // ws: 16 x 128 weights, float4
            int kk = t >> 3, cs = (t & 7) * 16;
            const float4* s4 = reinterpret_cast<const float4*>(W_er + (size_t)(k0 + kk) * MD + cs);
            float4* d4 = reinterpret_cast<float4*>(&ws[kk][cs]);
            #pragma unroll
            for (int j = 0; j < 4; j++) d4[j] = s4[j];
        }
        __syncthreads();
        #pragma unroll
        for (int kk = 0; kk < 16; kk++) {
            float4 w4 = *reinterpret_cast<const float4*>(&ws[kk][c0]);
            #pragma unroll
            for (int r = 0; r < 16; r++) {
                float xv = xs[rg * 16 + r][kk];
                acc[r][0] = fmaf(xv, w4.x, acc[r][0]);
                acc[r][1] = fmaf(xv, w4.y, acc[r][1]);
                acc[r][2] = fmaf(xv, w4.z, acc[r][2]);
                acc[r][3] = fmaf(xv, w4.w, acc[r][3]);
            }
        }
        __syncthreads();
    }
    { // ef = acc + b_er -> efs (float4 stores)
        float4 be = *reinterpret_cast<const float4*>(&b_er[c0]);
        #pragma unroll
        for (int r = 0; r < 16; r++) {
            float4 v = make_float4(acc[r][0]+be.x, acc[r][1]+be.y, acc[r][2]+be.z, acc[r][3]+be.w);
            *reinterpret_cast<float4*>(&efs[rg*16+r][c0]) = v;
        }
    }
    __syncthreads();

    // ---- stage 2: m_raw = relu(ef @ W_msg_bot + a_nf[w])  (K = 128) ----
    #pragma unroll
    for (int r = 0; r < 16; r++) { acc[r][0]=0.f; acc[r][1]=0.f; acc[r][2]=0.f; acc[r][3]=0.f; }
    for (int k0 = 0; k0 < MD; k0 += 16) {
        {
            int kk = t >> 3, cs = (t & 7) * 16;
            const float4* s4 = reinterpret_cast<const float4*>(W_msg + (size_t)(MD + k0 + kk) * MD + cs);
            float4* d4 = reinterpret_cast<float4*>(&ws[kk][cs]);
            #pragma unroll
            for (int j = 0; j < 4; j++) d4[j] = s4[j];
        }
        __syncthreads();
        #pragma unroll
        for (int kk = 0; kk < 16; kk++) {
            float4 w4 = *reinterpret_cast<const float4*>(&ws[kk][c0]);
            #pragma unroll
            for (int r = 0; r < 16; r++) {
                float xv = efs[rg * 16 + r][k0 + kk];
                acc[r][0] = fmaf(xv, w4.x, acc[r][0]);
                acc[r][1] = fmaf(xv, w4.y, acc[r][1]);
                acc[r][2] = fmaf(xv, w4.z, acc[r][2]);
                acc[r][3] = fmaf(xv, w4.w, acc[r][3]);
            }
        }
        __syncthreads();
    }
    #pragma unroll
    for (int r = 0; r < 16; r++) {
        int lr = rg * 16 + r;
        int ri = lr >> 4, wi = lr & 15;
        if (ri >= Vi || wi >= Vw) continue;
        const float4 a4 = *reinterpret_cast<const float4*>(
            g_anf + (size_t)(b * NN + w0 + wi) * MD + c0);
        float4 v = make_float4(fmaxf(acc[r][0]+a4.x, 0.f), fmaxf(acc[r][1]+a4.y, 0.f),
                               fmaxf(acc[r][2]+a4.z, 0.f), fmaxf(acc[r][3]+a4.w, 0.f));
        *reinterpret_cast<float4*>(g_mraw + (size_t)(ebase0 + ri*NN + wi) * MD + c0) = v;
    }

    // ---- stage 3: s0 = relu(ef @ W_l1 + b_l1) . W_l2 + b_l2 ----
    #pragma unroll
    for (int r = 0; r < 16; r++) { acc[r][0]=0.f; acc[r][1]=0.f; acc[r][2]=0.f; acc[r][3]=0.f; }
    for (int k0 = 0; k0 < MD; k0 += 16) {
        {
            int kk = t >> 3, cs = (t & 7) * 16;
            const float4* s4 = reinterpret_cast<const float4*>(W_l1 + (size_t)(k0 + kk) * MD + cs);
            float4* d4 = reinterpret_cast<float4*>(&ws[kk][cs]);
            #pragma unroll
            for (int j = 0; j < 4; j++) d4[j] = s4[j];
        }
        __syncthreads();
        #pragma unroll
        for (int kk = 0; kk < 16; kk++) {
            float4 w4 = *reinterpret_cast<const float4*>(&ws[kk][c0]);
            #pragma unroll
            for (int r = 0; r < 16; r++) {
                float xv = efs[rg * 16 + r][k0 + kk];
                acc[r][0] = fmaf(xv, w4.x, acc[r][0]);
                acc[r][1] = fmaf(xv, w4.y, acc[r][1]);
                acc[r][2] = fmaf(xv, w4.z, acc[r][2]);
                acc[r][3] = fmaf(xv, w4.w, acc[r][3]);
            }
        }
        __syncthreads();
    }
    {
        float4 bl = *reinterpret_cast<const float4*>(&b_l1[c0]);
        float4 u  = *reinterpret_cast<const float4*>(&W_l2[c0]);
        float bl2 = b_l2[0];
        #pragma unroll
        for (int r = 0; r < 16; r++) {
            float p = fmaxf(acc[r][0] + bl.x, 0.f) * u.x
                    + fmaxf(acc[r][1] + bl.y, 0.f) * u.y
                    + fmaxf(acc[r][2] + bl.z, 0.f) * u.z
                    + fmaxf(acc[r][3] + bl.w, 0.f) * u.w;
            #pragma unroll
            for (int o = 16; o > 0; o >>= 1) p += __shfl_xor_sync(0xffffffffu, p, o);
            int lr = rg * 16 + r;
            int ri = lr >> 4, wi = lr & 15;
            if (cg == 0 && ri < Vi && wi < Vw)
                g_sA[ebase0 + ri*NN + wi] = p + bl2;
        }
    }
}

// ---------------- rounds 1 & 2: s_next[i,w] = f(sigmoid(s_prev[w,i]) * m_raw[w,i]) ----------------
__global__ __launch_bounds__(128, 4) void k_round(
    int pass,
    const float* __restrict__ W_l1, const float* __restrict__ b_l1,
    const float* __restrict__ W_l2, const float* __restrict__ b_l2,
    float* __restrict__ out_adj)   // non-null on final pass
{
    const int b  = blockIdx.z;
    const int V  = g_valid[b];
    const int i0 = blockIdx.y * 4;
    const int w0 = blockIdx.x * 16;
    if (i0 >= V || w0 >= V) return;
    const int Vi = V - i0;
    const int Vw = V - w0;

    const float* sprev = (pass == 1) ? g_sA : g_sB;
    float*       snext = (pass == 1) ? g_sB : g_sA;

    const int t  = threadIdx.x;
    const int cg = t & 31;
    const int rg = t >> 5;
    const int c0 = cg * 4;

    __shared__ float vs[64][MD];   // 32 KB
    __shared__ float ws[16][MD];   // 8 KB

    // fill vs = gate * m_raw (transposed edge), float4 everywhere
    #pragma unroll
    for (int r = 0; r < 16; r++) {
        int lr = rg * 16 + r;
        int ri = lr >> 4, wi = lr & 15;
        float4 v = make_float4(0.f, 0.f, 0.f, 0.f);
        if (ri < Vi && wi < Vw) {
            int sed = (b * NN + w0 + wi) * NN + i0 + ri;   // transposed edge
            float g = sigmoidf_(sprev[sed]);
            float4 m = *reinterpret_cast<const float4*>(g_mraw + (size_t)sed * MD + c0);
            v = make_float4(g*m.x, g*m.y, g*m.z, g*m.w);
        }
        *reinterpret_cast<float4*>(&vs[lr][c0]) = v;
    }

    float acc[16][4];
    #pragma unroll
    for (int r = 0; r < 16; r++) { acc[r][0]=0.f; acc[r][1]=0.f; acc[r][2]=0.f; acc[r][3]=0.f; }

    for (int k0 = 0; k0 < MD; k0 += 16) {
        {
            int kk = t >> 3, cs = (t & 7) * 16;
            const float4* s4 = reinterpret_cast<const float4*>(W_l1 + (size_t)(k0 + kk) * MD + cs);
            float4* d4 = reinterpret_cast<float4*>(&ws[kk][cs]);
            #pragma unroll
            for (int j = 0; j < 4; j++) d4[j] = s4[j];
        }
        __syncthreads();
        #pragma unroll
        for (int kk = 0; kk < 16; kk++) {
            float4 w4 = *reinterpret_cast<const float4*>(&ws[kk][c0]);
            #pragma unroll
            for (int r = 0; r < 16; r++) {
                float xv = vs[rg * 16 + r][k0 + kk];
                acc[r][0] = fmaf(xv, w4.x, acc[r][0]);
                acc[r][1] = fmaf(xv, w4.y, acc[r][1]);
                acc[r][2] = fmaf(xv, w4.z, acc[r][2]);
                acc[r][3] = fmaf(xv, w4.w, acc[r][3]);
            }
        }
        __syncthreads();
    }
    {
        float4 bl = *reinterpret_cast<const float4*>(&b_l1[c0]);
        float4 u  = *reinterpret_cast<const float4*>(&W_l2[c0]);
        float bl2 = b_l2[0];
        #pragma unroll
        for (int r = 0; r < 16; r++) {
            float p = fmaxf(acc[r][0] + bl.x, 0.f) * u.x
                    + fmaxf(acc[r][1] + bl.y, 0.f) * u.y
                    + fmaxf(acc[r][2] + bl.z, 0.f) * u.z
                    + fmaxf(acc[r][3] + bl.w, 0.f) * u.w;
            #pragma unroll
            for (int o = 16; o > 0; o >>= 1) p += __shfl_xor_sync(0xffffffffu, p, o);
            int lr = rg * 16 + r;
            int ri = lr >> 4, wi = lr & 15;
            if (cg == 0 && ri < Vi && wi < Vw) {
                int d = (b * NN + i0 + ri) * NN + w0 + wi;
                float sv = p + bl2;
                snext[d] = sv;
                if (out_adj) out_adj[d] = sv;
            }
        }
    }
}

// ---------------- m_sum[b,i] = sum_w sigmoid(s2[i,w]) * m_raw[i,w,:] ----------------
__global__ __launch_bounds__(128) void k_msum() {
    const int b = blockIdx.y;
    const int i = blockIdx.x;
    const int V = g_valid[b];
    const int t = threadIdx.x;
    float a0 = 0.f, a1 = 0.f, a2 = 0.f, a3 = 0.f;
    if (i < V) {
        const float* sp = g_sA + (b * NN + i) * NN;   // s2 lives in g_sA after pass 2
        const float* mp = g_mraw + (size_t)(b * NN + i) * NN * MD;
        int w = 0;
        for (; w + 3 < V; w += 4) {
            float g0 = sigmoidf_(sp[w]);
            float g1 = sigmoidf_(sp[w + 1]);
            float g2 = sigmoidf_(sp[w + 2]);
            float g3 = sigmoidf_(sp[w + 3]);
            a0 = fmaf(g0, mp[(size_t)w * MD + t], a0);
            a1 = fmaf(g1, mp[(size_t)(w + 1) * MD + t], a1);
            a2 = fmaf(g2, mp[(size_t)(w + 2) * MD + t], a2);
            a3 = fmaf(g3, mp[(size_t)(w + 3) * MD + t], a3);
        }
        for (; w < V; w++) {
            float g0 = sigmoidf_(sp[w]);
            a0 = fmaf(g0, mp[(size_t)w * MD + t], a0);
        }
    }
    g_msum[(size_t)(b * NN + i) * MD + t] = (a0 + a1) + (a2 + a3);
}

// ---------------- GRU + readout, 8 nodes per block ----------------
__global__ __launch_bounds__(128) void k_gru(
    const float* __restrict__ W_ih, const float* __restrict__ b_ih,
    const float* __restrict__ W_hh, const float* __restrict__ b_hh,
    const float* __restrict__ W_ro, const float* __restrict__ b_ro,
    float* __restrict__ out)
{
    const int b  = blockIdx.y;
    const int V  = g_valid[b];
    const int i0 = blockIdx.x * 8;
    const int t  = threadIdx.x;

    __shared__ float ms[8][MD];
    __shared__ float hsn[8][MD];
    __shared__ float hnew[8][MD];

    #pragma unroll
    for (int n = 0; n < 8; n++) {
        ms[n][t]  = g_msum[(size_t)(b * NN + i0 + n) * MD + t];
        hsn[n][t] = g_nf[(size_t)(b * NN + i0 + n) * MD + t];
    }
    __syncthreads();

    float air[8], aiz[8], ain[8], ahr[8], ahz[8], ahn[8];
    {
        float bir = b_ih[t], biz = b_ih[128 + t], bin_ = b_ih[256 + t];
        float bhr = b_hh[t], bhz = b_hh[128 + t], bhn = b_hh[256 + t];
        #pragma unroll
        for (int n = 0; n < 8; n++) {
            air[n] = bir; aiz[n] = biz; ain[n] = bin_;
            ahr[n] = bhr; ahz[n] = bhz; ahn[n] = bhn;
        }
    }
    for (int k = 0; k < MD; k++) {
        float wr = W_ih[k * 384 + t];
        float wz = W_ih[k * 384 + 128 + t];
        float wn = W_ih[k * 384 + 256 + t];
        float vr = W_hh[k * 384 + t];
        float vz = W_hh[k * 384 + 128 + t];
        float vn = W_hh[k * 384 + 256 + t];
        #pragma unroll
        for (int n = 0; n < 8; n++) {
            float xv = ms[n][k], hv = hsn[n][k];
            air[n] = fmaf(xv, wr, air[n]);
            aiz[n] = fmaf(xv, wz, aiz[n]);
            ain[n] = fmaf(xv, wn, ain[n]);
            ahr[n] = fmaf(hv, vr, ahr[n]);
            ahz[n] = fmaf(hv, vz, ahz[n]);
            ahn[n] = fmaf(hv, vn, ahn[n]);
        }
    }
    #pragma unroll
    for (int n = 0; n < 8; n++) {
        float r  = sigmoidf_(air[n] + ahr[n]);
        float z  = sigmoidf_(aiz[n] + ahz[n]);
        float nn_ = tanhf(ain[n] + r * ahn[n]);
        hnew[n][t] = (1.f - z) * nn_ + z * hsn[n][t];
    }
    __syncthreads();

    // labels: 600 output classes, 5 column-blocks of 128
    float* lab = out + (size_t)BN * NN * NN;
    for (int cb = 0; cb < 5; cb++) {
        int c = cb * 128 + t;
        if (c >= CLS) continue;
        float lacc[8];
        #pragma unroll
        for (int n = 0; n < 8; n++) lacc[n] = 0.f;
        for (int k = 0; k < MD; k++) {
            float wv = W_ro[k * CLS + c];
            #pragma unroll
            for (int n = 0; n < 8; n++) lacc[n] = fmaf(hnew[n][k], wv, lacc[n]);
        }
        float bv = b_ro[c];
        #pragma unroll
        for (int n = 0; n < 8; n++) {
            int i = i0 + n;
            float v = (i < V) ? (lacc[n] + bv) : 0.f;
            lab[(size_t)(b * NN + i) * CLS + c] = v;
        }
    }
}

// ---------------- launcher ----------------
extern "C" void kernel_launch(void* const* d_in, const int* in_sizes, int n_in,
                              void* d_out, int out_size)
{
    const float* edge_features = (const float*)d_in[0];
    const float* node_features = (const float*)d_in[1];
    const int*   human = (const int*)d_in[4];
    const int*   obj   = (const int*)d_in[5];
    const float* W_er  = (const float*)d_in[6];
    const float* b_er  = (const float*)d_in[7];
    const float* W_nr  = (const float*)d_in[8];
    const float* b_nr  = (const float*)d_in[9];
    const float* W_l1  = (const float*)d_in[10];
    const float* b_l1  = (const float*)d_in[11];
    const float* W_l2  = (const float*)d_in[12];
    const float* b_l2  = (const float*)d_in[13];
    const float* W_msg = (const float*)d_in[14];
    const float* b_msg = (const float*)d_in[15];
    const float* W_ih  = (const float*)d_in[16];
    const float* b_ih  = (const float*)d_in[17];
    const float* W_hh  = (const float*)d_in[18];
    const float* b_hh  = (const float*)d_in[19];
    const float* W_ro  = (const float*)d_in[20];
    const float* b_ro  = (const float*)d_in[21];
    float* out = (float*)d_out;

    k_valid<<<1, 32>>>(human, obj);
    k_zero_adj<<<256, 256>>>(out);                 // BN*NN*NN/4 float4 exactly
    k_nodes<<<128, 128>>>(node_features, W_nr, b_nr, W_msg, b_msg);

    dim3 eg(NN / 16, NN / 4, BN);
    k_edge<<<eg, 128>>>(edge_features, W_er, b_er, W_msg, W_l1, b_l1, W_l2, b_l2);
    k_round<<<eg, 128>>>(1, W_l1, b_l1, W_l2, b_l2, nullptr);
    k_round<<<eg, 128>>>(2, W_l1, b_l1, W_l2, b_l2, out);   // writes pred_adj + s2 (g_sA)

    dim3 mg(NN, BN);
    k_msum<<<mg, 128>>>();
    k_gru<<<dim3(NN / 8, BN), 128>>>(W_ih, b_ih, W_hh, b_hh, W_ro, b_ro, out);
}